// round 17
// baseline (speedup 1.0000x reference)
#include <cuda_runtime.h>
#include <cuda_bf16.h>
#include <cuda_fp16.h>

// BoundaryLoss: loss = sum_{b,c,d,h,w} Gx(q)^2 + 2*Gy(q)^2 (normalized),
// q = softmax(pred, axis=C) - onehot(target); 2-D sobel per depth slice.
// pred (2,4,96,160,160) f32, target (2,96,160,160) i32.
// R17 = R15 (one wave, ring, fp16 q smem, half2 sobel, ch3-normalized
// softmax) with f16x2 ex2 over voxel pairs + fp32 rcp: 2.5 MUFU/voxel
// (R15 was 4.0). [R16's rcp.f16x2 does not exist in PTX.]

#define BB 2
#define CC 4
#define DD 96
#define HH 160
#define WW 160

#define TH 16                       // output rows per tile
#define HALO (TH + 2)               // 18 (ring size)
#define RTILES (HH / TH)            // 10
#define NTILE (BB * DD * RTILES)    // 1920
#define NPBLK 592                   // 148 SMs x 4 blocks, one wave
#define K4BLK 144                   // first 144 blocks take 4 tiles (rest 3)
#define NTHREADS 320
#define NWARP (NTHREADS / 32)
#define PITCHB 336                  // bytes/row: [4 guard][160 data][4 guard] halfs

#define CHSTR4 (DD * HH * WW / 4)

__device__ float g_partial[NPBLK];
__device__ int   g_count = 0;

__device__ __forceinline__ __half2 u2h(unsigned x) {
    return *reinterpret_cast<__half2*>(&x);
}
__device__ __forceinline__ unsigned h2u(__half2 x) {
    return *reinterpret_cast<unsigned*>(&x);
}
__device__ __forceinline__ unsigned h2ex2(unsigned x) {
    unsigned r; asm("ex2.approx.f16x2 %0, %1;" : "=r"(r) : "r"(x)); return r;
}
__device__ __forceinline__ float rcpa(float x) {
    float r; asm("rcp.approx.f32 %0, %1;" : "=f"(r) : "f"(x)); return r;
}

#define LOG2E 1.4426950408889634f
#define ONE_H2 0x3C003C00u

// onehot mask for voxel pair (ta,tb), class c: half 1.0 in matching lanes
__device__ __forceinline__ unsigned oh_mask(int ta, int tb, int c) {
    return (ta == c ? 0x3C00u : 0u) | (tb == c ? 0x3C000000u : 0u);
}

// one voxel pair -> 4 packed q half2 words (one per class)
__device__ __forceinline__ void softmax_pair(
    float x0a, float x1a, float x2a, float x3a, int ta,
    float x0b, float x1b, float x2b, float x3b, int tb,
    unsigned& w0, unsigned& w1, unsigned& w2, unsigned& w3)
{
    const float nba = -LOG2E * x3a;
    const float nbb = -LOG2E * x3b;
    const unsigned d0 = h2u(__floats2half2_rn(__fmaf_rn(x0a, LOG2E, nba),
                                              __fmaf_rn(x0b, LOG2E, nbb)));
    const unsigned d1 = h2u(__floats2half2_rn(__fmaf_rn(x1a, LOG2E, nba),
                                              __fmaf_rn(x1b, LOG2E, nbb)));
    const unsigned d2 = h2u(__floats2half2_rn(__fmaf_rn(x2a, LOG2E, nba),
                                              __fmaf_rn(x2b, LOG2E, nbb)));
    const __half2 e0 = u2h(h2ex2(d0));
    const __half2 e1 = u2h(h2ex2(d1));
    const __half2 e2 = u2h(h2ex2(d2));
    const __half2 s  = __hadd2(__hadd2(e0, e1), __hadd2(e2, u2h(ONE_H2)));
    const float2  sf = __half22float2(s);
    const __half2 r  = __floats2half2_rn(rcpa(sf.x), rcpa(sf.y));
    w0 = h2u(__hsub2(__hmul2(e0, r), u2h(oh_mask(ta, tb, 0))));
    w1 = h2u(__hsub2(__hmul2(e1, r), u2h(oh_mask(ta, tb, 1))));
    w2 = h2u(__hsub2(__hmul2(e2, r), u2h(oh_mask(ta, tb, 2))));
    w3 = h2u(__hsub2(r,              u2h(oh_mask(ta, tb, 3))));
}

// softmax(4) - onehot for a float4 item -> packed fp16, store at ring slot
__device__ __forceinline__ void softmax_store(
    unsigned char* qsm, const float4 x0, const float4 x1,
    const float4 x2, const float4 x3, const int4 tt, int slot, int vc)
{
    unsigned a0, a1, a2, a3, b0, b1, b2, b3;
    softmax_pair(x0.x, x1.x, x2.x, x3.x, tt.x,
                 x0.y, x1.y, x2.y, x3.y, tt.y, a0, a1, a2, a3);
    softmax_pair(x0.z, x1.z, x2.z, x3.z, tt.z,
                 x0.w, x1.w, x2.w, x3.w, tt.w, b0, b1, b2, b3);
    const int bo = 8 + 8 * vc + slot * PITCHB;
    *(uint2*)(qsm + 0 * HALO * PITCHB + bo) = make_uint2(a0, b0);
    *(uint2*)(qsm + 1 * HALO * PITCHB + bo) = make_uint2(a1, b1);
    *(uint2*)(qsm + 2 * HALO * PITCHB + bo) = make_uint2(a2, b2);
    *(uint2*)(qsm + 3 * HALO * PITCHB + bo) = make_uint2(a3, b3);
}

__device__ __forceinline__ void zero_store(unsigned char* qsm, int slot, int vc)
{
    const int bo = 8 + 8 * vc + slot * PITCHB;
    const uint2 z = make_uint2(0u, 0u);
    *(uint2*)(qsm + 0 * HALO * PITCHB + bo) = z;
    *(uint2*)(qsm + 1 * HALO * PITCHB + bo) = z;
    *(uint2*)(qsm + 2 * HALO * PITCHB + bo) = z;
    *(uint2*)(qsm + 3 * HALO * PITCHB + bo) = z;
}

__global__ __launch_bounds__(NTHREADS, 4)
void bl_main_kernel(const float* __restrict__ pred,
                    const int*   __restrict__ target,
                    float*       __restrict__ out)
{
    __shared__ __align__(16) unsigned char qsm[CC * HALO * PITCHB];  // 24192 B
    __shared__ float warpsum[NWARP];
    __shared__ double dwarpsum[NWARP];
    __shared__ bool  is_last;

    const int tid = threadIdx.x;

    // ---- tile range for this block (contiguous, one-wave layout) ----
    int t0, ntl;
    if (blockIdx.x < K4BLK) { t0 = blockIdx.x * 4;                       ntl = 4; }
    else                    { t0 = K4BLK * 4 + (blockIdx.x - K4BLK) * 3; ntl = 3; }

    // ---- guard halfs: zero [0..3] and [164..167] per (c,slot); once ----
    if (tid < CC * HALO * 2) {
        const int c    = tid / (HALO * 2);
        const int rem  = tid - c * (HALO * 2);
        const int row  = rem >> 1;
        const int side = rem & 1;
        *(uint2*)(qsm + (c * HALO + row) * PITCHB + (side ? 328 : 0)) = make_uint2(0u, 0u);
    }

    // phase-1 incremental mapping (fixed): jn = tid/40 (0..7), vc = tid%40
    const int jn1  = tid / 40;
    const int vcn  = tid - jn1 * 40;

    // phase-2 mapping: (class c2, 4-col group g2, 8-row strip s2); 4*40*2=320
    const int c2   = tid / 80;
    const int rem2 = tid - c2 * 80;
    const int s2   = rem2 / 40;
    const int g2   = rem2 - s2 * 40;
    const int off2 = 8 * g2;
    unsigned char* const base_c2 = qsm + c2 * HALO * PITCHB;

    float axs = 0.f, ays = 0.f;

    int cur_slice = -1;
    int rslot0 = 0;                 // ring slot of current tile's halo row 0

    for (int t = t0; t < t0 + ntl; t++) {
        const int rt    = t % RTILES;
        const int slice = t / RTILES;
        const int b     = slice / DD;
        const int d     = slice - b * DD;
        const int h0    = rt * TH;

        const float* pred_bd = pred + (size_t)(b * CC * DD + d) * (HH * WW);
        const int*   tgt_bd  = target + (size_t)slice * (HH * WW);

        if (slice != cur_slice) {
            // ---- full 18-row load into slots 0..17 ----
            cur_slice = slice;
            rslot0 = 0;
            for (int p = tid; p < HALO * (WW / 4); p += NTHREADS) {
                const int j  = p / (WW / 4);
                const int vc = p - j * (WW / 4);
                const int h  = h0 + j - 1;
                if ((unsigned)h < (unsigned)HH) {
                    const float4* pr = (const float4*)(pred_bd + h * WW) + vc;
                    softmax_store(qsm, pr[0], pr[CHSTR4], pr[2 * CHSTR4], pr[3 * CHSTR4],
                                  ((const int4*)(tgt_bd + h * WW))[vc], j, vc);
                } else {
                    zero_store(qsm, j, vc);
                }
            }
        } else {
            // ---- incremental: 16 new rows (this tile's halo rows 2..17) ----
            const int p = rslot0;                    // previous tile's slot0
            {
                const int h = h0 + 1 + jn1;          // <= h0+8 <= 152: valid
                int sl = p + jn1; if (sl >= HALO) sl -= HALO;
                const float4* pr = (const float4*)(pred_bd + h * WW) + vcn;
                softmax_store(qsm, pr[0], pr[CHSTR4], pr[2 * CHSTR4], pr[3 * CHSTR4],
                              ((const int4*)(tgt_bd + h * WW))[vcn], sl, vcn);
            }
            {
                const int jn2 = jn1 + 8;             // 8..15
                const int h = h0 + 1 + jn2;          // may be HH at rt==9
                int sl = p + jn2; if (sl >= HALO) sl -= HALO;
                if (h < HH) {
                    const float4* pr = (const float4*)(pred_bd + h * WW) + vcn;
                    softmax_store(qsm, pr[0], pr[CHSTR4], pr[2 * CHSTR4], pr[3 * CHSTR4],
                                  ((const int4*)(tgt_bd + h * WW))[vcn], sl, vcn);
                } else {
                    zero_store(qsm, sl, vcn);
                }
            }
            rslot0 = p + 16; if (rslot0 >= HALO) rslot0 -= HALO;
        }
        __syncthreads();

        // ---- Phase 2: separable sobel in packed half2, ring-slot walk ----
        {
            const __half2 TWOH = __half2half2(__float2half(2.0f));
            const __half2 ZERO = __half2half2(__float2half(0.0f));
            int sl = rslot0 + s2 * 8; if (sl >= HALO) sl -= HALO;

            __half2 pu[2], pv[2], cu[2], cv[2];

#define ROW_UV(U, V)                                                      \
    {                                                                     \
        const unsigned char* rp = base_c2 + sl * PITCHB;                  \
        const unsigned eL = *(const unsigned*)(rp + 4 + off2);            \
        const uint2    M  = *(const uint2*)(rp + 8 + off2);               \
        const unsigned eR = *(const unsigned*)(rp + 16 + off2);           \
        const __half2 S0 = u2h(__byte_perm(eL, M.x, 0x5432));             \
        const __half2 S1 = u2h(__byte_perm(M.x, M.y, 0x5432));            \
        const __half2 S2 = u2h(__byte_perm(M.y, eR, 0x5432));             \
        U[0] = __hfma2(u2h(M.x), TWOH, __hadd2(S0, S1));                  \
        U[1] = __hfma2(u2h(M.y), TWOH, __hadd2(S1, S2));                  \
        V[0] = __hsub2(S1, S0);                                           \
        V[1] = __hsub2(S2, S1);                                           \
        if (++sl == HALO) sl = 0;                                         \
    }

            ROW_UV(pu, pv);
            ROW_UV(cu, cv);

#pragma unroll
            for (int half_blk = 0; half_blk < 2; half_blk++) {
                __half2 axh = ZERO, ayh = ZERO;
#pragma unroll
                for (int k = 0; k < 4; k++) {
                    __half2 nu[2], nv[2];
                    ROW_UV(nu, nv);
#pragma unroll
                    for (int i = 0; i < 2; i++) {
                        const __half2 gx = __hfma2(cv[i], TWOH, __hadd2(pv[i], nv[i]));
                        const __half2 gy = __hsub2(nu[i], pu[i]);
                        axh = __hfma2(gx, gx, axh);
                        ayh = __hfma2(gy, gy, ayh);
                        pu[i] = cu[i]; pv[i] = cv[i];
                        cu[i] = nu[i]; cv[i] = nv[i];
                    }
                }
                const float2 fx = __half22float2(axh);
                const float2 fy = __half22float2(ayh);
                axs += fx.x + fx.y;
                ays += fy.x + fy.y;
            }
#undef ROW_UV
        }

        if (t + 1 < t0 + ntl) __syncthreads();   // ring overwrite hazard
    }

    float acc = axs + 2.f * ays;

    // ---- block reduction -> per-block partial ----
#pragma unroll
    for (int o = 16; o > 0; o >>= 1)
        acc += __shfl_down_sync(0xffffffffu, acc, o);
    if ((tid & 31) == 0) warpsum[tid >> 5] = acc;
    __syncthreads();

    if (tid == 0) {
        float sm = 0.f;
#pragma unroll
        for (int i = 0; i < NWARP; i++) sm += warpsum[i];
        g_partial[blockIdx.x] = sm;
        __threadfence();
        is_last = (atomicAdd(&g_count, 1) == NPBLK - 1);
    }
    __syncthreads();

    // ---- last block: final reduction + output + counter reset ----
    if (is_last) {
        double sd = 0.0;
        for (int i = tid; i < NPBLK; i += NTHREADS) sd += (double)g_partial[i];
#pragma unroll
        for (int o = 16; o > 0; o >>= 1)
            sd += __shfl_down_sync(0xffffffffu, sd, o);
        if ((tid & 31) == 0) dwarpsum[tid >> 5] = sd;
        __syncthreads();
        if (tid == 0) {
            double tot = 0.0;
#pragma unroll
            for (int i = 0; i < NWARP; i++) tot += dwarpsum[i];
            const double per_tensor = (double)BB * (DD + 2) * (HH + 2) * (WW + 2);
            out[0] = (float)(tot / per_tensor / (double)CC);
            g_count = 0;
        }
    }
}

extern "C" void kernel_launch(void* const* d_in, const int* in_sizes, int n_in,
                              void* d_out, int out_size)
{
    const float* pred   = (const float*)d_in[0];
    const int*   target = (const int*)d_in[1];
    float*       out    = (float*)d_out;

    bl_main_kernel<<<NPBLK, NTHREADS>>>(pred, target, out);
}